// round 15
// baseline (speedup 1.0000x reference)
#include <cuda_runtime.h>
#include <cuda_fp16.h>
#include <cstdint>

// GraphAttention fused, fp16 m16n8k16 + ldmatrix. 8 warps, 64x64 warp tiles,
// KC=64 (8 chunks), 2-stage pipeline. K0: Ww -> fp16 global.

#define B_ 256
#define C_ 128
#define T_ 512
#define H_ 256
#define KC 64
#define CHUNKS 8
#define THREADS 256

#define XROW 72              // stage row stride (halves); 144B = 4-bank step, conflict-free
#define HTROW 264            // h row-major stride (halves)
#define AROW 136             // alpha row stride (halves)

// byte offsets in dynamic smem
#define XS(s) ((s) * 18432)            // x stages: 2 x 128*72*2
#define WS(s) (36864 + (s) * 36864)    // W stages: 2 x 256*72*2
#define HT_OFF 0                       // h row-major 128 x 264 fp16 = 67584 (aliases stages)
#define AH_OFF 67584                   // alpha 128 x 136 fp16 = 34816
#define MISCB  110592
// misc f32 indices
#define M_WB   0
#define M_ASRC 256
#define M_ADST 512
#define M_FP   768           // 4 x 128
#define M_GP   1792          // 4 x 128
#define M_FV   2816
#define M_GV   2944
#define M_SP   3072          // 2 x 128
#define M_SINV 3584
#define M_AB   3712
#define SMEM_BYTES (MISCB + 3720 * 4)

__device__ __align__(16) __half g_wh[H_ * T_];

__device__ __forceinline__ uint32_t smem_u32(const void* p) {
    uint32_t a;
    asm("{ .reg .u64 t; cvta.to.shared.u64 t, %1; cvt.u32.u64 %0, t; }" : "=r"(a) : "l"(p));
    return a;
}
__device__ __forceinline__ void mma16(float* c, const uint32_t* a, const uint32_t* b) {
    asm volatile(
        "mma.sync.aligned.m16n8k16.row.col.f32.f16.f16.f32 "
        "{%0,%1,%2,%3}, {%4,%5,%6,%7}, {%8,%9}, {%0,%1,%2,%3};"
        : "+f"(c[0]), "+f"(c[1]), "+f"(c[2]), "+f"(c[3])
        : "r"(a[0]), "r"(a[1]), "r"(a[2]), "r"(a[3]), "r"(b[0]), "r"(b[1]));
}
__device__ __forceinline__ void ldm_x4(uint32_t* r, uint32_t addr) {
    asm volatile("ldmatrix.sync.aligned.m8n8.x4.shared.b16 {%0,%1,%2,%3}, [%4];"
        : "=r"(r[0]), "=r"(r[1]), "=r"(r[2]), "=r"(r[3]) : "r"(addr));
}
__device__ __forceinline__ void ldm_x4_t(uint32_t* r, uint32_t addr) {
    asm volatile("ldmatrix.sync.aligned.m8n8.x4.trans.shared.b16 {%0,%1,%2,%3}, [%4];"
        : "=r"(r[0]), "=r"(r[1]), "=r"(r[2]), "=r"(r[3]) : "r"(addr));
}
__device__ __forceinline__ uint32_t pack2(float lo, float hi) {
    __half2 h = __floats2half2_rn(lo, hi);
    return *(const uint32_t*)&h;
}
#define CP_ASYNC16(dst, src) \
    asm volatile("cp.async.cg.shared.global [%0], [%1], 16;" :: "r"(dst), "l"(src) : "memory")
#define CP_COMMIT() asm volatile("cp.async.commit_group;" ::: "memory")
#define CP_WAIT(n)  asm volatile("cp.async.wait_group %0;" :: "n"(n) : "memory")

// ---------------- K0: Ww fp32 -> fp16 ----------------
__global__ void k0_convw(const float* __restrict__ Ww) {
    int i = blockIdx.x * 256 + threadIdx.x;   // grid (H_*T_)/256 = 512
    g_wh[i] = __float2half_rn(Ww[i]);
}

// ---------------- Main fused kernel ----------------
__global__ __launch_bounds__(THREADS, 1)
void gat_p(const float* __restrict__ x, const float* __restrict__ Wb,
           const float* __restrict__ aw, const float* __restrict__ ab,
           float* __restrict__ out)
{
    extern __shared__ char smc[];
    float* misc = (float*)(smc + MISCB);
    const uint32_t smb = smem_u32(smc);

    const int tid  = threadIdx.x;
    const int lane = tid & 31;
    const int warp = tid >> 5;
    const int wr   = warp >> 2;      // 0..1: 64-row block
    const int wc   = warp & 3;       // 0..3: 64-col block
    const int lq   = lane >> 2;
    const int lk   = lane & 3;
    const int b    = blockIdx.x;

    const int lrow = lane & 7, ga = (lane >> 3) & 1, gb = lane >> 4;
    const uint32_t a_roff = (uint32_t)(lrow + ga * 8);
    const uint32_t a_koff = (uint32_t)(gb * 8);
    const uint32_t b_roff = (uint32_t)(lrow + gb * 8);
    const uint32_t b_koff = (uint32_t)(ga * 8);

    const float* xb = x + (size_t)b * C_ * T_;

    if (tid < 256) {
        misc[M_WB + tid]   = Wb[tid];
        misc[M_ASRC + tid] = aw[tid];
        misc[M_ADST + tid] = aw[H_ + tid];
    }
    if (tid == 0) misc[M_AB] = ab[0];

    // x: chunk = 128 rows x 64 cols fp32 = 2048 float4 -> 8 per thread, packed at LDG.
    uint2 px[8];
    auto ldgx = [&](int c) {
        #pragma unroll
        for (int i = 0; i < 8; i++) {
            int id = tid + i * THREADS;                // < 2048
            int row = id >> 4, slot = id & 15;
            float4 v = *(const float4*)(xb + row * T_ + c * KC + slot * 4);
            px[i].x = pack2(v.x, v.y);
            px[i].y = pack2(v.z, v.w);
        }
    };
    auto stsx = [&](int stage) {
        #pragma unroll
        for (int i = 0; i < 8; i++) {
            int id = tid + i * THREADS;
            int row = id >> 4, slot = id & 15;
            *(uint2*)(smc + XS(stage) + row * 144 + slot * 8) = px[i];
        }
    };
    auto cpaw = [&](int c, int stage) {
        #pragma unroll
        for (int i = 0; i < 8; i++) {
            int id = tid + i * THREADS;                // < 2048
            int row = id >> 3, q = id & 7;             // 256 rows x 8 x 16B
            CP_ASYNC16(smb + (uint32_t)(WS(stage) + row * 144 + q * 16),
                       g_wh + row * T_ + c * KC + q * 8);
        }
        CP_COMMIT();
    };

    float acc[4][8][4];
    #pragma unroll
    for (int mb = 0; mb < 4; mb++)
        #pragma unroll
        for (int nb = 0; nb < 8; nb++)
            #pragma unroll
            for (int q = 0; q < 4; q++) acc[mb][nb][q] = 0.f;

    // prologue: stage chunk 0, prefetch chunk 1 in regs, W chunk 0 in flight
    ldgx(0);
    stsx(0);
    cpaw(0, 0);
    ldgx(1);
    CP_WAIT(0);
    __syncthreads();

    // ---- Phase 1: h = x @ Ww^T ----
    #pragma unroll
    for (int c = 0; c < CHUNKS; c++) {
        if (c + 1 < CHUNKS) {
            stsx((c + 1) & 1);                  // px holds chunk c+1
            cpaw(c + 1, (c + 1) & 1);
            if (c + 2 < CHUNKS) ldgx(c + 2);    // refill px (WAR after STS issue: safe)
        }

        const uint32_t xs_u = smb + (uint32_t)XS(c & 1);
        const uint32_t ws_u = smb + (uint32_t)WS(c & 1);

        #pragma unroll
        for (int kq = 0; kq < 4; kq++) {
            const uint32_t k0 = (uint32_t)(kq * 16);
            uint32_t afr[4][4];
            #pragma unroll
            for (int mb = 0; mb < 4; mb++)
                ldm_x4(afr[mb],
                    xs_u + (((uint32_t)(wr * 64 + mb * 16) + a_roff) * XROW + k0 + a_koff) * 2u);
            uint32_t bfr[4][4];
            #pragma unroll
            for (int nbp = 0; nbp < 4; nbp++)
                ldm_x4(bfr[nbp],
                    ws_u + (((uint32_t)(wc * 64 + nbp * 16) + b_roff) * XROW + k0 + b_koff) * 2u);
            #pragma unroll
            for (int mb = 0; mb < 4; mb++)
                #pragma unroll
                for (int nbp = 0; nbp < 4; nbp++) {
                    mma16(acc[mb][2 * nbp],     afr[mb], &bfr[nbp][0]);
                    mma16(acc[mb][2 * nbp + 1], afr[mb], &bfr[nbp][2]);
                }
        }
        if (c + 1 < CHUNKS) CP_WAIT(0);
        __syncthreads();
    }

    // ---- Epilogue 1: bias, f/g partials, h row-major fp16 (stride 264) ----
    {
        __half* ht = (__half*)(smc + HT_OFF);
        #pragma unroll
        for (int mb = 0; mb < 4; mb++) {
            #pragma unroll
            for (int hf = 0; hf < 2; hf++) {
                int r = wr * 64 + mb * 16 + lq + hf * 8;
                float f_ = 0.f, g_ = 0.f;
                #pragma unroll
                for (int nb = 0; nb < 8; nb++) {
                    int col = wc * 64 + nb * 8 + 2 * lk;
                    float h0 = acc[mb][nb][hf * 2 + 0] + misc[M_WB + col];
                    float h1 = acc[mb][nb][hf * 2 + 1] + misc[M_WB + col + 1];
                    f_ += h0 * misc[M_ASRC + col] + h1 * misc[M_ASRC + col + 1];
                    g_ += h0 * misc[M_ADST + col] + h1 * misc[M_ADST + col + 1];
                    *(uint32_t*)(ht + r * HTROW + col) = pack2(h0, h1);
                }
                f_ += __shfl_xor_sync(0xFFFFFFFF, f_, 1);
                f_ += __shfl_xor_sync(0xFFFFFFFF, f_, 2);
                g_ += __shfl_xor_sync(0xFFFFFFFF, g_, 1);
                g_ += __shfl_xor_sync(0xFFFFFFFF, g_, 2);
                if (lk == 0) {
                    misc[M_FP + wc * 128 + r] = f_;
                    misc[M_GP + wc * 128 + r] = g_;
                }
            }
        }
    }
    __syncthreads();
    if (tid < 128) {
        float s = 0.f;
        #pragma unroll
        for (int p = 0; p < 4; p++) s += misc[M_FP + p * 128 + tid];
        misc[M_FV + tid] = s;
    } else {
        int r = tid - 128;
        float s = 0.f;
        #pragma unroll
        for (int p = 0; p < 4; p++) s += misc[M_GP + p * 128 + r];
        misc[M_GV + r] = s;
    }
    __syncthreads();

    // ---- Phase 2: softmax over i; alpha fp16 row-major [i][k=j] ----
    {
        __half* ah = (__half*)(smc + AH_OFF);
        const int j = tid & 127, part = tid >> 7;   // 2 parts x 64 i
        const float gj = misc[M_GV + j] + misc[M_AB];
        float s = 0.f;
        const int i0 = part * 64;
        #pragma unroll 4
        for (int i = i0; i < i0 + 64; i++) {
            float z = misc[M_FV + i] + gj;
            z = (z > 0.f) ? z : 0.2f * z;
            float ex = __expf(z);
            ah[i * AROW + j] = __float2half_rn(ex);
            s += ex;
        }
        misc[M_SP + part * 128 + j] = s;
        __syncthreads();
        if (tid < 128)
            misc[M_SINV + tid] = 1.0f / (misc[M_SP + tid] + misc[M_SP + 128 + tid]);
        __syncthreads();
        const float iv = misc[M_SINV + j];
        #pragma unroll 4
        for (int i = i0; i < i0 + 64; i++) {
            __half* p = ah + i * AROW + j;
            *p = __float2half_rn(__half2float(*p) * iv);
        }
    }
    __syncthreads();

    // ---- Phase 3: out = alpha @ h ----
    #pragma unroll
    for (int mb = 0; mb < 4; mb++)
        #pragma unroll
        for (int nb = 0; nb < 8; nb++)
            #pragma unroll
            for (int q = 0; q < 4; q++) acc[mb][nb][q] = 0.f;

    {
        const uint32_t ah_u = smb + AH_OFF;
        const uint32_t ht_u = smb + HT_OFF;
        #pragma unroll 2
        for (int kq = 0; kq < 8; kq++) {
            const uint32_t k0 = (uint32_t)(kq * 16);
            uint32_t afr[4][4];
            #pragma unroll
            for (int mb = 0; mb < 4; mb++)
                ldm_x4(afr[mb],
                    ah_u + (((uint32_t)(wr * 64 + mb * 16) + a_roff) * AROW + k0 + a_koff) * 2u);
            uint32_t bfr[4][4];
            #pragma unroll
            for (int nbp = 0; nbp < 4; nbp++)
                ldm_x4_t(bfr[nbp],
                    ht_u + ((k0 + a_roff) * HTROW + (uint32_t)(wc * 64 + nbp * 16 + gb * 8)) * 2u);
            #pragma unroll
            for (int mb = 0; mb < 4; mb++)
                #pragma unroll
                for (int nbp = 0; nbp < 4; nbp++) {
                    mma16(acc[mb][2 * nbp],     afr[mb], &bfr[nbp][0]);
                    mma16(acc[mb][2 * nbp + 1], afr[mb], &bfr[nbp][2]);
                }
        }
    }

    // ---- Epilogue 2: store out ----
    {
        float* ob = out + (size_t)b * C_ * H_;
        #pragma unroll
        for (int mb = 0; mb < 4; mb++) {
            int r  = wr * 64 + mb * 16 + lq;
            int r2 = r + 8;
            #pragma unroll
            for (int nb = 0; nb < 8; nb++) {
                int j0 = wc * 64 + nb * 8 + 2 * lk;
                *(float2*)&ob[r  * H_ + j0] = make_float2(acc[mb][nb][0], acc[mb][nb][1]);
                *(float2*)&ob[r2 * H_ + j0] = make_float2(acc[mb][nb][2], acc[mb][nb][3]);
            }
        }
    }
}

extern "C" void kernel_launch(void* const* d_in, const int* in_sizes, int n_in,
                              void* d_out, int out_size)
{
    const float* x  = (const float*)d_in[0];
    const float* Ww = (const float*)d_in[1];
    const float* Wb = (const float*)d_in[2];
    const float* aw = (const float*)d_in[3];
    const float* ab = (const float*)d_in[4];
    float* out = (float*)d_out;

    cudaFuncSetAttribute(gat_p, cudaFuncAttributeMaxDynamicSharedMemorySize, SMEM_BYTES);

    k0_convw<<<(H_ * T_) / 256, 256>>>(Ww);
    gat_p<<<B_, THREADS, SMEM_BYTES>>>(x, Wb, aw, ab, out);
}